// round 8
// baseline (speedup 1.0000x reference)
#include <cuda_runtime.h>
#include <cstddef>
#include <cstdint>

// VarConvND: 4096 independent GEMMs [64x288]x[288x16], tf32 MMA.
// m = C_OUT(16), n = batch(64), warps split K (72 rows each).
//   out[b,c,s] = sum_k u[b,k]*w[k,c] + bias[s]*sum_k w[k,c]

#define S_TOT 4096
#define KK    288
#define CO    16
#define CI    32
#define BB    64
#define HH    64
#define WW    64
#define P_TOT (CI*HH*WW)        // 131072
#define AST   72                // smA k-row stride (words): frag read hits 32 banks

// smem word map
#define SMA_WORDS (KK*AST)              // 20736
#define PAD_OFF   SMA_WORDS
#define PAD_WORDS (4*8*32*4)            // 4096
#define PADC_OFF  (PAD_OFF + PAD_WORDS) // +64
#define SMEM_BYTES ((PADC_OFF + 64) * 4)   // 99584

__device__ float g_Xt[(size_t)P_TOT * BB];        // X^T, tf32-rounded, [p][b]
__device__ float g_Os[(size_t)S_TOT * BB * CO];   // out scratch [s][b*16+c]

__device__ __forceinline__ unsigned f2tf(float f)
{
    unsigned u;
    asm("cvt.rna.tf32.f32 %0, %1;" : "=r"(u) : "f"(f));
    return u;
}

// ---------------- transpose + tf32-round: X[b][p] -> Xt[p][b] ----------------
__global__ void transpose_in(const float* __restrict__ X, float* __restrict__ Xt)
{
    __shared__ float t[32][33];
    const int tx = threadIdx.x, ty = threadIdx.y;
    const int p0 = blockIdx.x * 32, b0 = blockIdx.y * 32;
    #pragma unroll
    for (int i = 0; i < 32; i += 8)
        t[ty + i][tx] = X[(size_t)(b0 + ty + i) * P_TOT + p0 + tx];
    __syncthreads();
    #pragma unroll
    for (int i = 0; i < 32; i += 8) {
        unsigned u = f2tf(t[tx][ty + i]);
        Xt[(size_t)(p0 + ty + i) * BB + b0 + tx] = __uint_as_float(u);
    }
}

// ---------------- output transpose: Os[s][bc] -> out[bc][s] ----------------
__global__ void transpose_out(const float* __restrict__ Os, float* __restrict__ out)
{
    __shared__ float t[32][33];
    const int tx = threadIdx.x, ty = threadIdx.y;
    const int bc0 = blockIdx.x * 32, s0 = blockIdx.y * 32;
    #pragma unroll
    for (int i = 0; i < 32; i += 8)
        t[ty + i][tx] = Os[(size_t)(s0 + ty + i) * (BB * CO) + bc0 + tx];
    __syncthreads();
    #pragma unroll
    for (int i = 0; i < 32; i += 8)
        out[(size_t)(bc0 + ty + i) * S_TOT + s0 + tx] = t[tx][ty + i];
}

// ---------------- main kernel ----------------
__device__ __forceinline__ void cp16(unsigned dst, const void* src, bool ok)
{
    int sz = ok ? 16 : 0;
    asm volatile("cp.async.cg.shared.global [%0], [%1], 16, %2;\n"
                 :: "r"(dst), "l"(src), "r"(sz) : "memory");
}

__global__ __launch_bounds__(128)
void varconv_mma(const float* __restrict__ Wg,
                 const float* __restrict__ bias,
                 float* __restrict__ Os)
{
    extern __shared__ float smf[];

    const int s    = blockIdx.x;
    const int y    = s >> 6;
    const int x    = s & 63;
    const int tid  = threadIdx.x;
    const int lane = tid & 31;
    const int w    = tid >> 5;      // warp = K-quarter

    // ---- stage this warp's 72 k-rows of X (tf32 bits) via cp.async ----
    {
        const unsigned smbase = (unsigned)__cvta_generic_to_shared(smf);
        const int rsub = lane >> 3;       // 0..3
        const int csub = lane & 7;        // chunk low
        #pragma unroll
        for (int i = 0; i < 18; i++) {
            const int r  = i * 4 + rsub;          // 0..71
            const int kg = w * 72 + r;            // global k row
            const int cl  = kg / 9;
            const int tap = kg - cl * 9;
            const int t3  = tap / 3;
            const int yy  = y + t3 - 1;
            const int xx  = x + (tap - t3 * 3) - 1;
            const bool ok = ((unsigned)yy < (unsigned)HH) & ((unsigned)xx < (unsigned)WW);
            const float* src = ok
                ? g_Xt + ((size_t)((cl << 12) + (yy << 6) + xx) << 6)
                : g_Xt;
            const unsigned dstrow = smbase + (unsigned)(kg * AST) * 4u;
            #pragma unroll
            for (int j = 0; j < 2; j++) {
                const int chunk = csub + 8 * j;   // 0..15 (16B units)
                cp16(dstrow + chunk * 16, src + chunk * 4, ok);
            }
        }
        asm volatile("cp.async.commit_group;\n" ::: "memory");
    }

    // W fragment offsets (A = W^T, m16k8 row-major fragment)
    const float* wp  = Wg + (size_t)s * (KK * CO);
    const int woff   = ((lane & 3) << 4) + (lane >> 2);   // k*16 + c

    asm volatile("cp.async.wait_group 0;\n" ::: "memory");
    __syncwarp();

    float acc[8][4] = {};
    float cs0 = 0.f, cs1 = 0.f;

    #pragma unroll
    for (int i = 0; i < 9; i++) {
        const int ks = w * 9 + i;
        const float* wk = wp + ks * 128;
        const float wa0 = wk[woff];
        const float wa1 = wk[woff + 8];
        const float wa2 = wk[woff + 64];
        const float wa3 = wk[woff + 72];
        cs0 += wa0 + wa2;
        cs1 += wa1 + wa3;
        const unsigned A0 = f2tf(wa0), A1 = f2tf(wa1);
        const unsigned A2 = f2tf(wa2), A3 = f2tf(wa3);

        const int krow = (ks * 8 + (lane & 3)) * AST + (lane >> 2);
        #pragma unroll
        for (int nt = 0; nt < 8; nt++) {
            const unsigned b0 = __float_as_uint(smf[krow + nt * 8]);
            const unsigned b1 = __float_as_uint(smf[krow + 4 * AST + nt * 8]);
            asm volatile(
                "mma.sync.aligned.m16n8k8.row.col.f32.tf32.tf32.f32 "
                "{%0,%1,%2,%3}, {%4,%5,%6,%7}, {%8,%9}, {%0,%1,%2,%3};"
                : "+f"(acc[nt][0]), "+f"(acc[nt][1]),
                  "+f"(acc[nt][2]), "+f"(acc[nt][3])
                : "r"(A0), "r"(A1), "r"(A2), "r"(A3),
                  "r"(b0), "r"(b1));
        }
    }

    // ---- colsum partials: sum over this warp's k-range, per c ----
    cs0 += __shfl_xor_sync(0xffffffffu, cs0, 1);
    cs0 += __shfl_xor_sync(0xffffffffu, cs0, 2);
    cs1 += __shfl_xor_sync(0xffffffffu, cs1, 1);
    cs1 += __shfl_xor_sync(0xffffffffu, cs1, 2);
    if ((lane & 3) == 0) {
        smf[PADC_OFF + w * 16 + (lane >> 2)]     = cs0;   // c = lane>>2
        smf[PADC_OFF + w * 16 + 8 + (lane >> 2)] = cs1;   // c + 8
    }

    // ---- dump D fragments to pad (conflict-free STS.128) ----
    #pragma unroll
    for (int nt = 0; nt < 8; nt++) {
        float4 v = make_float4(acc[nt][0], acc[nt][1], acc[nt][2], acc[nt][3]);
        *(float4*)&smf[PAD_OFF + (((w * 8 + nt) * 32 + lane) << 2)] = v;
    }
    __syncthreads();

    // ---- reduce 4 K-partials + bias term, write coalesced scratch ----
    {
        const float bval = bias[s];
        const int c  = tid & 15;
        const int bg = tid >> 4;          // n-tile == b>>3
        const float csum = smf[PADC_OFF + c]      + smf[PADC_OFF + 16 + c]
                         + smf[PADC_OFF + 32 + c] + smf[PADC_OFF + 48 + c];
        const float bterm = bval * csum;
        float* os = Os + (size_t)s * (BB * CO);
        #pragma unroll
        for (int i = 0; i < 8; i++) {
            const int b = bg * 8 + i;
            const int l = ((c & 7) << 2) | (i >> 1);
            const int j = ((c >> 3) << 1) | (i & 1);
            float r = 0.f;
            #pragma unroll
            for (int ww = 0; ww < 4; ww++)
                r += smf[PAD_OFF + (((ww * 8 + bg) * 32 + l) << 2) + j];
            os[b * CO + c] = r + bterm;
        }
    }
}

extern "C" void kernel_launch(void* const* d_in, const int* in_sizes, int n_in,
                              void* d_out, int out_size)
{
    const float* X    = (const float*)d_in[0];
    const float* Wg   = (const float*)d_in[1];
    const float* bias = (const float*)d_in[2];
    float* out        = (float*)d_out;
    (void)in_sizes; (void)n_in; (void)out_size;

    float *Xt = nullptr, *Os = nullptr;
    cudaGetSymbolAddress((void**)&Xt, g_Xt);
    cudaGetSymbolAddress((void**)&Os, g_Os);

    cudaFuncSetAttribute(varconv_mma,
                         cudaFuncAttributeMaxDynamicSharedMemorySize, SMEM_BYTES);

    dim3 tb(32, 8);
    transpose_in<<<dim3(P_TOT / 32, BB / 32), tb>>>(X, Xt);

    varconv_mma<<<S_TOT, 128, SMEM_BYTES>>>(Wg, bias, Os);

    transpose_out<<<dim3((BB * CO) / 32, S_TOT / 32), tb>>>(Os, out);
}

// round 9
// speedup vs baseline: 1.7828x; 1.7828x over previous
#include <cuda_runtime.h>
#include <cstddef>
#include <cstdint>

// VarConvND: 4096 independent GEMMs [B=64 x K=288] x [K=288 x C_OUT=16].
// tf32 MMA, warps split batch (m-tiles), K double-buffered via cp.async.
//   out[b,c,s] = sum_k u[b,k]*w[k,c] + bias[s]*sum_k w[k,c]

#define S_TOT 4096
#define KK    288
#define CO    16
#define CI    32
#define BB    64
#define HH    64
#define WW    64
#define P_TOT (CI*HH*WW)            // 131072

#define AST   72                    // X chunk row stride (words) -> 32-bank frag reads
#define WST   24                    // W row stride (words)       -> 32-bank frag reads
#define WF_WORDS  (KK*WST)          // 6912
#define BUF_WORDS (72*AST)          // 5184
#define BUF0_OFF  WF_WORDS
#define BUF1_OFF  (WF_WORDS + BUF_WORDS)
#define CPAD_OFF  (WF_WORDS + 2*BUF_WORDS)
#define CSUM_OFF  (CPAD_OFF + 128)
#define SMEM_WORDS (CSUM_OFF + 16)
#define SMEM_BYTES (SMEM_WORDS * 4)   // 69696

__device__ float g_Xt[(size_t)P_TOT * BB];        // X^T, tf32-rounded, [p][b]
__device__ float g_Os[(size_t)S_TOT * BB * CO];   // out scratch [s][b*16+c]

__device__ __forceinline__ unsigned f2tf(float f)
{
    unsigned u;
    asm("cvt.rna.tf32.f32 %0, %1;" : "=r"(u) : "f"(f));
    return u;
}

// ---------- transpose + tf32-round: X[b][p] -> Xt[p][b], vectorized ----------
__global__ __launch_bounds__(256)
void transpose_in(const float* __restrict__ X, float* __restrict__ Xt)
{
    __shared__ float tt[64][65];
    const int tid = threadIdx.x;
    const int p0  = blockIdx.x * 64;

    #pragma unroll
    for (int i = 0; i < 4; i++) {
        const int u = tid + 256 * i;
        const int b = u >> 4;
        const int q = u & 15;
        float4 v = *(const float4*)(X + (size_t)b * P_TOT + p0 + 4 * q);
        tt[4 * q + 0][b] = v.x;
        tt[4 * q + 1][b] = v.y;
        tt[4 * q + 2][b] = v.z;
        tt[4 * q + 3][b] = v.w;
    }
    __syncthreads();
    #pragma unroll
    for (int i = 0; i < 4; i++) {
        const int u  = tid + 256 * i;
        const int p  = u >> 4;
        const int bq = u & 15;
        float4 o;
        o.x = __uint_as_float(f2tf(tt[p][4 * bq + 0]));
        o.y = __uint_as_float(f2tf(tt[p][4 * bq + 1]));
        o.z = __uint_as_float(f2tf(tt[p][4 * bq + 2]));
        o.w = __uint_as_float(f2tf(tt[p][4 * bq + 3]));
        *(float4*)(Xt + (size_t)(p0 + p) * BB + 4 * bq) = o;
    }
}

// ---------- output transpose: Os[s][bc] -> out[bc][s] ----------
__global__ void transpose_out(const float* __restrict__ Os, float* __restrict__ out)
{
    __shared__ float t[32][33];
    const int tx = threadIdx.x, ty = threadIdx.y;
    const int bc0 = blockIdx.x * 32, s0 = blockIdx.y * 32;
    #pragma unroll
    for (int i = 0; i < 32; i += 8)
        t[ty + i][tx] = Os[(size_t)(s0 + ty + i) * (BB * CO) + bc0 + tx];
    __syncthreads();
    #pragma unroll
    for (int i = 0; i < 32; i += 8)
        out[(size_t)(bc0 + ty + i) * S_TOT + s0 + tx] = t[tx][ty + i];
}

// ---------- main kernel ----------
__device__ __forceinline__ void cp16(unsigned dst, const void* src, bool ok)
{
    int sz = ok ? 16 : 0;
    asm volatile("cp.async.cg.shared.global [%0], [%1], 16, %2;\n"
                 :: "r"(dst), "l"(src), "r"(sz) : "memory");
}
#define CP_COMMIT() asm volatile("cp.async.commit_group;\n" ::: "memory")
#define CP_WAIT(N)  asm volatile("cp.async.wait_group %0;\n" :: "n"(N) : "memory")

__global__ __launch_bounds__(128)
void varconv_mma(const float* __restrict__ Wg,
                 const float* __restrict__ bias,
                 float* __restrict__ Os)
{
    extern __shared__ float smf[];
    const unsigned smb = (unsigned)__cvta_generic_to_shared(smf);

    const int s    = blockIdx.x;
    const int y    = s >> 6;
    const int x    = s & 63;
    const int tid  = threadIdx.x;
    const int lane = tid & 31;
    const int wid  = tid >> 5;

    const float* wp = Wg + (size_t)s * (KK * CO);

    // ---- stage X chunk (72 k-rows x 64 batches, tf32 bits) via cp.async ----
    auto stage_x = [&](int chunk, int bufoff) {
        const int r0 = tid >> 4;          // 0..7
        const int q  = tid & 15;          // 16B unit within row
        #pragma unroll
        for (int i = 0; i < 9; i++) {
            const int r   = r0 + 8 * i;   // 0..71
            const int k   = chunk * 72 + r;
            const int cl  = k / 9;
            const int tap = k - cl * 9;
            const int t3  = tap / 3;
            const int yy  = y + t3 - 1;
            const int xx  = x + (tap - 3 * t3) - 1;
            const bool ok = ((unsigned)yy < (unsigned)HH) & ((unsigned)xx < (unsigned)WW);
            const float* src = ok
                ? g_Xt + ((size_t)((cl << 12) + (yy << 6) + xx) << 6) + q * 4
                : g_Xt;
            cp16(smb + (unsigned)(bufoff + r * AST + q * 4) * 4u, src, ok);
        }
    };

    // ---- stage W (288x16 fp32, row stride 24) via cp.async ----
    {
        const int k0 = tid >> 2;          // 0..31
        const int q  = tid & 3;           // 16B unit (4 c's)
        #pragma unroll
        for (int i = 0; i < 9; i++) {
            const int k = k0 + 32 * i;
            cp16(smb + (unsigned)(k * WST + q * 4) * 4u, wp + k * CO + q * 4, true);
        }
    }
    stage_x(0, BUF0_OFF);
    CP_COMMIT();                          // group0 = W + chunk0
    stage_x(1, BUF1_OFF);
    CP_COMMIT();                          // group1 = chunk1

    // fragment-role constants
    const int cc  = lane & 3;
    const int r4  = lane >> 2;
    const int aoff = cc * AST + wid * 16 + r4;   // + i*576 (+8 / +288)
    const int woff = cc * WST + r4;              // + nt*8 (+96), + (chunk*72+i*8)*24

    float acc[2][4] = {};

    auto compute = [&](int bufoff, int chunk) {
        #pragma unroll
        for (int i = 0; i < 9; i++) {
            const int ab = bufoff + i * (8 * AST) + aoff;
            const unsigned a0 = __float_as_uint(smf[ab]);
            const unsigned a1 = __float_as_uint(smf[ab + 8]);
            const unsigned a2 = __float_as_uint(smf[ab + 4 * AST]);
            const unsigned a3 = __float_as_uint(smf[ab + 4 * AST + 8]);
            const int wb = (chunk * 72 + i * 8) * WST + woff;
            #pragma unroll
            for (int nt = 0; nt < 2; nt++) {
                const unsigned b0 = f2tf(smf[wb + nt * 8]);
                const unsigned b1 = f2tf(smf[wb + nt * 8 + 4 * WST]);
                asm volatile(
                    "mma.sync.aligned.m16n8k8.row.col.f32.tf32.tf32.f32 "
                    "{%0,%1,%2,%3}, {%4,%5,%6,%7}, {%8,%9}, {%0,%1,%2,%3};"
                    : "+f"(acc[nt][0]), "+f"(acc[nt][1]),
                      "+f"(acc[nt][2]), "+f"(acc[nt][3])
                    : "r"(a0), "r"(a1), "r"(a2), "r"(a3),
                      "r"(b0), "r"(b1));
            }
        }
    };

    CP_WAIT(1); __syncthreads();          // W + chunk0 visible
    compute(BUF0_OFF, 0);
    __syncthreads();
    stage_x(2, BUF0_OFF); CP_COMMIT();

    CP_WAIT(1); __syncthreads();          // chunk1 visible
    compute(BUF1_OFF, 1);
    __syncthreads();
    stage_x(3, BUF1_OFF); CP_COMMIT();

    CP_WAIT(1); __syncthreads();          // chunk2 visible
    compute(BUF0_OFF, 2);

    CP_WAIT(0); __syncthreads();          // chunk3 visible
    compute(BUF1_OFF, 3);

    // ---- colsum[c] = sum_k w[k][c] (raw fp32) ----
    {
        const int c   = tid & 15;
        const int seg = tid >> 4;         // 0..7 -> 36 k each
        float p = 0.f;
        #pragma unroll
        for (int kk = 0; kk < 36; kk++)
            p += smf[(seg * 36 + kk) * WST + c];
        smf[CPAD_OFF + seg * 16 + c] = p;
    }
    __syncthreads();
    if (tid < 16) {
        float sum = 0.f;
        #pragma unroll
        for (int j = 0; j < 8; j++) sum += smf[CPAD_OFF + j * 16 + tid];
        smf[CSUM_OFF + tid] = sum;
    }
    __syncthreads();

    // ---- epilogue: D frag -> Os[s][b*16+c] ----
    {
        const float bval = bias[s];
        float* os = Os + (size_t)s * (BB * CO);
        #pragma unroll
        for (int nt = 0; nt < 2; nt++) {
            #pragma unroll
            for (int j = 0; j < 4; j++) {
                const int c = nt * 8 + 2 * cc + (j & 1);
                const int b = wid * 16 + r4 + (j >> 1) * 8;
                os[b * CO + c] = acc[nt][j] + bval * smf[CSUM_OFF + c];
            }
        }
    }
}

extern "C" void kernel_launch(void* const* d_in, const int* in_sizes, int n_in,
                              void* d_out, int out_size)
{
    const float* X    = (const float*)d_in[0];
    const float* Wg   = (const float*)d_in[1];
    const float* bias = (const float*)d_in[2];
    float* out        = (float*)d_out;
    (void)in_sizes; (void)n_in; (void)out_size;

    float *Xt = nullptr, *Os = nullptr;
    cudaGetSymbolAddress((void**)&Xt, g_Xt);
    cudaGetSymbolAddress((void**)&Os, g_Os);

    cudaFuncSetAttribute(varconv_mma,
                         cudaFuncAttributeMaxDynamicSharedMemorySize, SMEM_BYTES);

    transpose_in<<<P_TOT / 64, 256>>>(X, Xt);

    varconv_mma<<<S_TOT, 128, SMEM_BYTES>>>(Wg, bias, Os);

    dim3 tb(32, 8);
    transpose_out<<<dim3((BB * CO) / 32, S_TOT / 32), tb>>>(Os, out);
}